// round 17
// baseline (speedup 1.0000x reference)
#include <cuda_runtime.h>
#include <cuda_bf16.h>
#include <mma.h>
#include <math.h>
#include <cstdint>

using namespace nvcuda;

// ---------------------------------------------------------------------------
// DifferentiableModalPlate, round 15 — WMMA (HMMA) GEMM factorization.
//   t = 32g + d:  u_m(t) = a_m(g)*[e^{-d sigK} cos(d w)] + b_m(g)*[e^{-d sigK} sin(d w)]
//   disp[704 x 32] = A[704 x 12800] * B[12800 x 32]
// bf16 hi/lo split of both A and B, 3 accumulation passes (AhBh+AhBl+AlBh),
// fp32 accumulators. tcgen05 is unavailable (harness targets generic sm_103),
// so the tensor work goes through wmma/mma.sync bf16 which compiles on
// compute_103 and runs on the tensor pipe (FMA-pipe floor ~26us bypassed).
// ---------------------------------------------------------------------------

#define MODES  6400
#define MMAXI  80
#define KDIM   12800          // k = 2m (sin-part), 2m+1 (cos-part)
#define MROWS  768            // A rows allocated (704 used)
#define GROWS  704
#define TROW   22528          // 704*32
#define NSEG   16             // A-gen segments (48 g-rows each)
#define KSPL   32
#define KCH    (KDIM / KSPL)  // 400 (25 k-steps of 16)
#define MBLK   11             // 64 rows per block
#define FBLK   176

__device__ float4  g_modeC[MODES];                 // {w1s, -sigK*log2e, lc, P}
__device__ float   g_modeQ[MODES];
__device__ __nv_bfloat16 g_Ah[MROWS][KDIM];        // 19.7 MB
__device__ __nv_bfloat16 g_Al[MROWS][KDIM];        // 19.7 MB
__device__ __nv_bfloat16 g_Bh[KDIM][32];           // 0.8 MB
__device__ __nv_bfloat16 g_Bl[KDIM][32];
__device__ float   g_Cpart[KSPL][GROWS][32];       // 2.9 MB
__device__ unsigned g_peak_bits, g_cnt;

__device__ __forceinline__ float ex2a(float x) {
    float y; asm("ex2.approx.f32 %0, %1;" : "=f"(y) : "f"(x)); return y;
}
__device__ __forceinline__ float softplus_ref(float x) {
    return fmaxf(x, 0.0f) + log1pf(expf(-fabsf(x)));
}
__device__ __forceinline__ float sigmoid_ref(float x) {
    if (x >= 0.0f) { float e = expf(-x); return 1.0f / (1.0f + e); }
    float e = expf(x); return e / (1.0f + e);
}

// ---- per-mode params (validated in R6-R9): w1s, sigK, lc = log2|coef| ------
__device__ void mode_params(int i,
                            const float* mu_raw, const float* Dmu_raw,
                            const float* T0mu_raw, const float* Ly_raw,
                            const float* xo_raw, const float* yo_raw,
                            float* o_w1s, float* o_sigK, float* o_lc)
{
    const float K_F   = (float)(1.0 / 44100.0);
    const float KK_F  = (float)((1.0 / 44100.0) * (1.0 / 44100.0));
    const float PI_F  = (float)M_PI;
    const float XIPI  = (float)((0.1 * 0.5) * M_PI);
    const float MAXOM = (float)(10000.0 * 2.0 * M_PI);
    const float MINOM = (float)(20.0 * 2.0 * M_PI);
    const double OM2SQ_D = (2.0 * M_PI * 500.0) * (2.0 * M_PI * 500.0);
    const float ALPHA_F = (float)(3.0 * log(10.0) / OM2SQ_D * (OM2SQ_D / 6.0));
    const float BETA_F  = (float)(3.0 * log(10.0) / OM2SQ_D * (1.0 / 1.0 - 1.0 / 6.0));

    float mu  = __fmul_rn(__fadd_rn(softplus_ref(*mu_raw),   1e-4f), 2.43f);
    float Dm  = __fmul_rn(__fadd_rn(softplus_ref(*Dmu_raw),  1e-4f), 0.002452f);
    float T0m = __fmul_rn(__fadd_rn(softplus_ref(*T0mu_raw), 1e-4f), 0.004115f);
    float Ly  = __fadd_rn(1.1f, __fmul_rn((float)(4.0 - 1.1), sigmoid_ref(*Ly_raw)));
    float xo  = __fadd_rn((float)(0.49 * 0.5),
                          __fmul_rn((float)((1.0 - 0.49) * 0.5), sigmoid_ref(*xo_raw)));
    float yo  = __fadd_rn(__fmul_rn(0.51f, Ly),
                          __fmul_rn(__fmul_rn((float)(1.0 - 0.51), Ly), sigmoid_ref(*yo_raw)));
    float yi  = __fmul_rn(0.1f, Ly);
    float ms  = __fmul_rn(__fmul_rn(__fmul_rn(0.25f, mu), 0.5f), Ly);

    float mf = (float)(i / MMAXI + 1);
    float nf = (float)(i % MMAXI + 1);
    float a = __fdiv_rn(__fmul_rn(mf, PI_F), 0.5f);
    float b = __fdiv_rn(__fmul_rn(nf, PI_F), Ly);
    float g1 = __fadd_rn(__fmul_rn(a, a), __fmul_rn(b, b));
    float osq = __fadd_rn(__fmul_rn(T0m, g1), __fmul_rn(__fmul_rn(Dm, g1), g1));
    float omega = sqrtf(fmaxf(osq, 0.0f));
    float valid = (omega <= MAXOM && omega >= MINOM) ? 1.0f : 0.0f;

    float InW = __fmul_rn(
        cosf(__fdiv_rn(__fmul_rn(XIPI, mf), 0.5f)),
        cosf(__fdiv_rn(__fmul_rn(__fmul_rn(yi, PI_F), nf), Ly)));
    float OutW = __fmul_rn(
        cosf(__fdiv_rn(__fmul_rn(__fmul_rn(xo, PI_F), mf), 0.5f)),
        cosf(__fdiv_rn(__fmul_rn(__fmul_rn(yo, PI_F), nf), Ly)));

    float sigma = __fadd_rn(ALPHA_F, __fmul_rn(BETA_F, __fmul_rn(omega, omega)));
    float e0 = expf(__fmul_rn(-sigma, K_F));
    float P = __fmul_rn(
        __fdiv_rn(__fmul_rn(__fmul_rn(__fmul_rn(OutW, InW), KK_F), e0), ms), valid);

    float w1   = __fmul_rn(omega, K_F);
    float den  = __fadd_rn(sinf(w1), 1e-8f);
    float coef = __fdiv_rn(P, den);
    float sigK = __fmul_rn(sigma, K_F);

    *o_w1s  = (coef < 0.0f) ? -w1 : w1;
    *o_sigK = sigK;
    *o_lc   = log2f(fabsf(coef));   // -inf when coef == 0 -> E = 0
}

// ---- K1: prep — mode constants + B tables ----------------------------------
__global__ void __launch_bounds__(128)
plate_prep_kernel(const float* mu_raw, const float* Dmu_raw,
                  const float* T0mu_raw, const float* Ly_raw,
                  const float* xo_raw, const float* yo_raw)
{
    int k = blockIdx.x * 128 + threadIdx.x;     // 0..12799
    if (k == 0) { g_peak_bits = 0u; g_cnt = 0u; }
    int m   = k >> 1;
    int isS = k & 1;                             // 0: cos row (pairs a), 1: sin row (pairs b)

    float w1s, sigK, lc;
    mode_params(m, mu_raw, Dmu_raw, T0mu_raw, Ly_raw, xo_raw, yo_raw,
                &w1s, &sigK, &lc);

    if (!isS) {
        float e32 = expf(-32.0f * sigK);
        float P = e32 * cosf(32.0f * w1s);
        float Q = e32 * sinf(32.0f * w1s);
        g_modeC[m] = make_float4(w1s, -sigK * 1.4426950408889634f, lc, P);
        g_modeQ[m] = Q;
    }

    // B[k][d] = rho^d * (cos|sin)(d*w1s), d in [0,32)
    float rho = expf(-sigK);
    float cw = cosf(w1s), sw = sinf(w1s);
    float vc = 1.0f, vs = 0.0f;
    __nv_bfloat16* bh = g_Bh[k];
    __nv_bfloat16* bl = g_Bl[k];
    #pragma unroll 4
    for (int d = 0; d < 32; ++d) {
        float v = isS ? vs : vc;
        __nv_bfloat16 h = __float2bfloat16_rn(v);
        __nv_bfloat16 l = __float2bfloat16_rn(v - __bfloat162float(h));
        bh[d] = h;
        bl[d] = l;
        float nvc = rho * fmaf(vc, cw, -(vs * sw));
        float nvs = rho * fmaf(vc, sw,  (vs * cw));
        vc = nvc; vs = nvs;
    }
}

// ---- K2: A-gen — seed per segment, 48 rotation steps -----------------------
// A[g][2m]   = a(g) = E sin(32 g w)   (pairs with cos row of B)
// A[g][2m+1] = b(g) = E cos(32 g w)   (pairs with sin row of B)
__global__ void __launch_bounds__(128)
plate_agen_kernel()
{
    const float TWOOPI = 0.63661977236758134f;
    const float TPI_HI = 6.283185482025146484375f;
    const float TPI_LO = -1.7484555e-7f;

    int m = blockIdx.x * 128 + threadIdx.x;     // 0..6399
    int s = blockIdx.y;                          // 0..15
    float4 C = g_modeC[m];
    float Q = g_modeQ[m];
    float P = C.w;

    float t0f = 1536.0f * (float)s;
    float ph = t0f * C.x;
    float q  = rintf(ph * TWOOPI);
    float r  = fmaf(q, -TPI_HI, ph);
    r        = fmaf(q, -TPI_LO, r);
    float E  = ex2a(fmaf(t0f - 1.0f, C.y, C.z));
    float a = E * __sinf(r);
    float b = E * __cosf(r);

    int g0 = 48 * s;
    #pragma unroll 4
    for (int j = 0; j < 48; ++j) {
        __nv_bfloat16 ah = __float2bfloat16_rn(a);
        __nv_bfloat16 bh = __float2bfloat16_rn(b);
        __nv_bfloat16 al = __float2bfloat16_rn(a - __bfloat162float(ah));
        __nv_bfloat16 bl = __float2bfloat16_rn(b - __bfloat162float(bh));
        uint32_t hp = ((uint32_t)__bfloat16_as_ushort(bh) << 16) | __bfloat16_as_ushort(ah);
        uint32_t lp = ((uint32_t)__bfloat16_as_ushort(bl) << 16) | __bfloat16_as_ushort(al);
        *reinterpret_cast<uint32_t*>(&g_Ah[g0 + j][2 * m]) = hp;
        *reinterpret_cast<uint32_t*>(&g_Al[g0 + j][2 * m]) = lp;
        float na = fmaf(P, a,  Q * b);          // rotate by 32 samples + decay
        float nb = fmaf(P, b, -(Q * a));
        a = na; b = nb;
    }
}

// ---- K3: WMMA GEMM — 11 M-blocks (64 rows) x 32 K-splits -------------------
__global__ void __launch_bounds__(128)
plate_gemm_kernel()
{
    int warp = threadIdx.x >> 5;
    int row0 = blockIdx.x * 64 + warp * 16;      // 0..688
    int ks   = blockIdx.y;                        // 0..31
    int k0   = ks * KCH;

    wmma::fragment<wmma::accumulator, 16, 16, 16, float> c0, c1;
    wmma::fill_fragment(c0, 0.0f);
    wmma::fill_fragment(c1, 0.0f);

    wmma::fragment<wmma::matrix_a, 16, 16, 16, __nv_bfloat16, wmma::row_major> a_h, a_l;
    wmma::fragment<wmma::matrix_b, 16, 16, 16, __nv_bfloat16, wmma::row_major> b_h0, b_h1, b_l0, b_l1;

    #pragma unroll 1
    for (int kk = k0; kk < k0 + KCH; kk += 16) {
        wmma::load_matrix_sync(a_h, &g_Ah[row0][kk], KDIM);
        wmma::load_matrix_sync(a_l, &g_Al[row0][kk], KDIM);
        wmma::load_matrix_sync(b_h0, &g_Bh[kk][0],  32);
        wmma::load_matrix_sync(b_h1, &g_Bh[kk][16], 32);
        wmma::load_matrix_sync(b_l0, &g_Bl[kk][0],  32);
        wmma::load_matrix_sync(b_l1, &g_Bl[kk][16], 32);

        wmma::mma_sync(c0, a_h, b_h0, c0);
        wmma::mma_sync(c1, a_h, b_h1, c1);
        wmma::mma_sync(c0, a_h, b_l0, c0);
        wmma::mma_sync(c1, a_h, b_l1, c1);
        wmma::mma_sync(c0, a_l, b_h0, c0);
        wmma::mma_sync(c1, a_l, b_h1, c1);
    }

    wmma::store_matrix_sync(&g_Cpart[ks][row0][0],  c0, 32, wmma::mem_row_major);
    wmma::store_matrix_sync(&g_Cpart[ks][row0][16], c1, 32, wmma::mem_row_major);
}

// ---- K4: combine K-splits + peak + normalize (grid barrier) ----------------
__global__ void __launch_bounds__(128)
plate_finish_kernel(float* __restrict__ out, int T)
{
    int t = blockIdx.x * 128 + threadIdx.x;      // 0..22527
    int gg = t >> 5, dd = t & 31;

    float v = 0.0f;
    #pragma unroll
    for (int s = 0; s < KSPL; ++s) v += g_Cpart[s][gg][dd];

    float av = (t < T) ? fabsf(v) : 0.0f;
    unsigned b = __reduce_max_sync(0xffffffffu, __float_as_uint(av));
    if ((threadIdx.x & 31) == 0) atomicMax(&g_peak_bits, b);

    __syncthreads();
    if (threadIdx.x == 0) {
        __threadfence();
        atomicAdd(&g_cnt, 1u);
        while (*((volatile unsigned*)&g_cnt) < (unsigned)FBLK) __nanosleep(64);
    }
    __syncthreads();

    float peak = __uint_as_float(*((volatile unsigned*)&g_peak_bits));
    if (t < T)
        out[t] = __fdiv_rn(v, __fadd_rn(peak, 1e-8f));
}

// ---------------------------------------------------------------------------
extern "C" void kernel_launch(void* const* d_in, const int* in_sizes, int n_in,
                              void* d_out, int out_size)
{
    const float* mu_raw   = (const float*)d_in[0];
    const float* Dmu_raw  = (const float*)d_in[1];
    const float* T0mu_raw = (const float*)d_in[2];
    const float* Ly_raw   = (const float*)d_in[3];
    const float* xo_raw   = (const float*)d_in[4];
    const float* yo_raw   = (const float*)d_in[5];
    float* out = (float*)d_out;

    int T = out_size;
    if (T > TROW) T = TROW;

    plate_prep_kernel<<<KDIM / 128, 128>>>(mu_raw, Dmu_raw, T0mu_raw,
                                           Ly_raw, xo_raw, yo_raw);
    plate_agen_kernel<<<dim3(MODES / 128, NSEG), 128>>>();
    plate_gemm_kernel<<<dim3(MBLK, KSPL), 128>>>();
    plate_finish_kernel<<<FBLK, 128>>>(out, T);
}